// round 3
// baseline (speedup 1.0000x reference)
#include <cuda_runtime.h>
#include <math.h>
#include <stdint.h>

#define BNB   8
#define C     64
#define NPTS  16384
#define KNBR  32
#define CN    256
#define CLEN  32
#define NCURVE (BNB*CN)     // 2048
#define WBLK  128           // walk grid blocks (<= #SMs, guaranteed co-resident)
#define WTPB  512
#define WPB   16            // warps (=curves) per block; WBLK*WPB == NCURVE

// ---------------- device scratch (no allocations allowed) ----------------
__device__ float  g_xw[(size_t)BNB*NPTS*C];   // point-major gated features [bn*n][c]
__device__ float  g_att[BNB*NPTS];
__device__ int    g_start[NCURVE];
__device__ float  g_mm[BNB*2*CN];             // raw momentum logits (for scrambled softmax)
__device__ double g_asums[WBLK][2];
__device__ double g_msums[WBLK][4];
__device__ volatile int g_flags[WBLK];
__device__ volatile int g_release;

// ---------------- helpers ----------------
__device__ __forceinline__ float warpsum(float v) {
    #pragma unroll
    for (int o = 16; o; o >>= 1) v += __shfl_down_sync(0xFFFFFFFFu, v, o);
    return __shfl_sync(0xFFFFFFFFu, v, 0);
}
__device__ __forceinline__ double warpsumd(double v) {
    #pragma unroll
    for (int o = 16; o; o >>= 1) v += __shfl_down_sync(0xFFFFFFFFu, v, o);
    return __shfl_sync(0xFFFFFFFFu, v, 0);
}

__device__ __forceinline__ void grid_barrier(int &epoch, int tid) {
    __syncthreads();
    ++epoch;
    if (tid == 0) { __threadfence(); g_flags[blockIdx.x] = epoch; }
    if (blockIdx.x == 0) {
        if (tid < WBLK) { while (g_flags[tid] < epoch) { } }
        __syncthreads();
        if (tid == 0) { __threadfence(); g_release = epoch; }
    }
    if (tid == 0) { while (g_release < epoch) { } __threadfence(); }
    __syncthreads();
}

// ---------------- kernel 1: x_att + transposed gated features ----------------
__global__ void k_xw(const float* __restrict__ x, const float* __restrict__ att_w) {
    __shared__ float sx[64][65];
    __shared__ float satt[64];
    __shared__ float sw[64];
    const int tid = threadIdx.x;
    const int b  = blockIdx.x >> 8;
    const int n0 = (blockIdx.x & 255) * 64;
    if (tid < 64) sw[tid] = att_w[tid];
    for (int i = tid; i < 64 * 64; i += 256) {
        int c = i >> 6, nn = i & 63;
        sx[c][nn] = x[((size_t)(b * C + c)) * NPTS + n0 + nn];
    }
    __syncthreads();
    if (tid < 64) {
        float s = 0.f;
        #pragma unroll
        for (int c = 0; c < 64; ++c) s += sx[c][tid] * sw[c];
        float a = 1.f / (1.f + expf(-s));
        satt[tid] = a;
        g_att[b * NPTS + n0 + tid] = a;
    }
    __syncthreads();
    for (int i = tid; i < 64 * 64; i += 256) {
        int nn = i >> 6, c = i & 63;
        g_xw[((size_t)(b * NPTS + n0 + nn)) * C + c] = sx[c][nn] * satt[nn];
    }
}

// ---------------- kernel 2: exact sorted top-256 per batch (bitonic) --------
__global__ void k_topk() {
    extern __shared__ unsigned long long sk[];
    const int tid = threadIdx.x;
    const int b = blockIdx.x;
    for (int i = tid; i < NPTS; i += blockDim.x) {
        unsigned u = __float_as_uint(g_att[b * NPTS + i]);
        u = (u & 0x80000000u) ? ~u : (u | 0x80000000u);   // order-preserving map
        sk[i] = ((unsigned long long)u << 32) | (unsigned)(NPTS - 1 - i);
    }
    __syncthreads();
    for (int k = 2; k <= NPTS; k <<= 1) {
        for (int jj = k >> 1; jj > 0; jj >>= 1) {
            for (int i = tid; i < NPTS; i += blockDim.x) {
                int ixj = i ^ jj;
                if (ixj > i) {
                    bool up = ((i & k) == 0);
                    unsigned long long a = sk[i], c = sk[ixj];
                    if ((a > c) == up) { sk[i] = c; sk[ixj] = a; }
                }
            }
            __syncthreads();
        }
    }
    if (tid < CN) {
        unsigned long long kk = sk[NPTS - 1 - tid];     // rank tid (desc, ties->min idx)
        g_start[b * CN + tid] = NPTS - 1 - (int)(unsigned)(kk & 0xFFFFFFFFull);
    }
}

// ---------------- kernel 3: reset barrier state ----------------
__global__ void k_init() {
    int t = threadIdx.x;
    if (t < WBLK) g_flags[t] = 0;
    if (t == 0) g_release = 0;
}

// ---------------- kernel 4: persistent curve walk ----------------
struct SW {
    float  tile[WPB][KNBR][20];  // per-warp neighbor chunk tile (pad 20 -> conflict-free)
    float  pre[WPB][C];
    float  cur[WPB][C];
    float  aw[2 * C];
    float  mw[4 * C];
    double red[WPB][4];
    float  bn[4];
};

__global__ void __launch_bounds__(WTPB, 1) k_walk(
    const int* __restrict__ idx,
    const float* __restrict__ agent_w,
    const float* __restrict__ agent_gp, const float* __restrict__ agent_bp,
    const float* __restrict__ mom_w,
    const float* __restrict__ mom_gp, const float* __restrict__ mom_bp,
    float* __restrict__ out)
{
    extern __shared__ char smraw[];
    SW* sm = (SW*)smraw;
    const unsigned F = 0xFFFFFFFFu;
    const int tid = threadIdx.x;
    const int w = tid >> 5;
    const int lane = tid & 31;

    for (int i = tid; i < 2 * C; i += WTPB) sm->aw[i] = agent_w[i];
    for (int i = tid; i < 4 * C; i += WTPB) sm->mw[i] = mom_w[i];
    __syncthreads();
    const float ag = agent_gp[0], ab = agent_bp[0];
    const float mg0 = mom_gp[0], mg1 = mom_gp[1], mb0 = mom_bp[0], mb1 = mom_bp[1];

    const int cid = blockIdx.x * WPB + w;   // curve id 0..2047
    const int b = cid >> 8;
    const int j = cid & 255;
    int epoch = 0;

    int fcur = b * NPTS + g_start[cid];
    sm->pre[w][lane]      = g_xw[(size_t)fcur * C + lane];
    sm->pre[w][lane + 32] = g_xw[(size_t)fcur * C + lane + 32];
    __syncwarp();

    const int jj4 = lane >> 2;
    const int q4  = (lane & 3) * 4;

    for (int t = 0; t < CLEN; ++t) {
        const bool useD = (t > 0);

        // ---------- momentum gate (steps >= 1) ----------
        if (useD) {
            float cu1 = sm->cur[w][lane],      cu2 = sm->cur[w][lane + 32];
            float pr1 = sm->pre[w][lane],      pr2 = sm->pre[w][lane + 32];
            float m0 = cu1 * sm->mw[lane]       + cu2 * sm->mw[32 + lane]
                     + pr1 * sm->mw[64 + lane]  + pr2 * sm->mw[96 + lane];
            float m1 = cu1 * sm->mw[128 + lane] + cu2 * sm->mw[160 + lane]
                     + pr1 * sm->mw[192 + lane] + pr2 * sm->mw[224 + lane];
            m0 = warpsum(m0); m1 = warpsum(m1);
            if (lane == 0) {
                g_mm[b * 512 + j]       = m0;
                g_mm[b * 512 + 256 + j] = m1;
                sm->red[w][0] = (double)m0; sm->red[w][1] = (double)m0 * m0;
                sm->red[w][2] = (double)m1; sm->red[w][3] = (double)m1 * m1;
            }
            __syncthreads();
            if (w == 0) {
                double r0 = (lane < WPB) ? sm->red[lane][0] : 0.0;
                double r1 = (lane < WPB) ? sm->red[lane][1] : 0.0;
                double r2 = (lane < WPB) ? sm->red[lane][2] : 0.0;
                double r3 = (lane < WPB) ? sm->red[lane][3] : 0.0;
                r0 = warpsumd(r0); r1 = warpsumd(r1); r2 = warpsumd(r2); r3 = warpsumd(r3);
                if (lane == 0) {
                    g_msums[blockIdx.x][0] = r0; g_msums[blockIdx.x][1] = r1;
                    g_msums[blockIdx.x][2] = r2; g_msums[blockIdx.x][3] = r3;
                }
            }
            grid_barrier(epoch, tid);
            if (w == 0) {
                double s0 = 0, q0 = 0, s1 = 0, q1 = 0;
                for (int i = lane; i < WBLK; i += 32) {
                    s0 += g_msums[i][0]; q0 += g_msums[i][1];
                    s1 += g_msums[i][2]; q1 += g_msums[i][3];
                }
                s0 = warpsumd(s0); q0 = warpsumd(q0); s1 = warpsumd(s1); q1 = warpsumd(q1);
                if (lane == 0) {
                    double mean0 = s0 / 2048.0, var0 = q0 / 2048.0 - mean0 * mean0;
                    double mean1 = s1 / 2048.0, var1 = q1 / 2048.0 - mean1 * mean1;
                    float r0f = (float)(1.0 / sqrt(var0 + 1e-5));
                    float r1f = (float)(1.0 / sqrt(var1 + 1e-5));
                    sm->bn[0] = r0f * mg0; sm->bn[1] = mb0 - (float)mean0 * r0f * mg0;
                    sm->bn[2] = r1f * mg1; sm->bn[3] = mb1 - (float)mean1 * r1f * mg1;
                }
            }
            __syncthreads();
            // scrambled attention weights (torch .view reshape semantics)
            float att = 0.f;
            if (lane < 2) {
                int f  = 2 * j + lane;          // flat index into [2,256] per batch
                int ch = f >> 8, jj = f & 255;
                float v0 = g_mm[b * 512 + jj]       * sm->bn[0] + sm->bn[1];
                float v1 = g_mm[b * 512 + 256 + jj] * sm->bn[2] + sm->bn[3];
                float mx = fmaxf(v0, v1);
                float e0 = expf(v0 - mx), e1 = expf(v1 - mx);
                att = ((ch == 0) ? e0 : e1) / (e0 + e1);
            }
            float att0 = __shfl_sync(F, att, 0);
            float att1 = __shfl_sync(F, att, 1);
            sm->pre[w][lane]      = cu1 * att0 + pr1 * att1;
            sm->pre[w][lane + 32] = cu2 * att0 + pr2 * att1;
            __syncwarp();
        }

        // ---------- agent logits + crossover ----------
        int myg = b * NPTS + idx[(size_t)fcur * KNBR + lane];
        float pd = sm->pre[w][lane] * sm->aw[C + lane]
                 + sm->pre[w][lane + 32] * sm->aw[C + lane + 32];
        pd = warpsum(pd);
        float anorm = 0.f;
        if (useD) {
            float a1 = sm->cur[w][lane] - sm->pre[w][lane];
            float a2 = sm->cur[w][lane + 32] - sm->pre[w][lane + 32];
            anorm = sqrtf(warpsum(a1 * a1 + a2 * a2));
        }
        float logit = pd, dotv = 0.f, n2 = 0.f;
        #pragma unroll
        for (int chunk = 0; chunk < 4; ++chunk) {
            const int c0 = chunk * 16;
            #pragma unroll
            for (int pass = 0; pass < 4; ++pass) {
                int src = jj4 + pass * 8;
                int g = __shfl_sync(F, myg, src);
                float4 v = *(const float4*)&g_xw[(size_t)g * C + c0 + q4];
                *(float4*)&sm->tile[w][src][q4] = v;
            }
            __syncwarp();
            #pragma unroll
            for (int cc = 0; cc < 16; cc += 4) {
                float4 pv  = *(const float4*)&sm->tile[w][lane][cc];
                float4 awv = *(const float4*)&sm->aw[c0 + cc];
                logit += pv.x * awv.x; logit += pv.y * awv.y;
                logit += pv.z * awv.z; logit += pv.w * awv.w;
                if (useD) {
                    float4 cu = *(const float4*)&sm->cur[w][c0 + cc];
                    float4 pr = *(const float4*)&sm->pre[w][c0 + cc];
                    float dx;
                    dx = pv.x - cu.x; dotv += (cu.x - pr.x) * dx; n2 += dx * dx;
                    dx = pv.y - cu.y; dotv += (cu.y - pr.y) * dx; n2 += dx * dx;
                    dx = pv.z - cu.z; dotv += (cu.z - pr.z) * dx; n2 += dx * dx;
                    dx = pv.w - cu.w; dotv += (cu.w - pr.w) * dx; n2 += dx * dx;
                }
            }
            __syncwarp();
        }
        float dfac = 1.f;
        if (useD) {
            float div = fmaxf(anorm * sqrtf(n2), 1e-8f);
            dfac = fminf(fmaxf(1.f + dotv / div, 0.f), 1.f);
        }

        // ---------- global BN over all 65536 logits ----------
        double ls = warpsumd((double)logit);
        double l2 = warpsumd((double)logit * (double)logit);
        if (lane == 0) { sm->red[w][0] = ls; sm->red[w][1] = l2; }
        __syncthreads();
        if (w == 0) {
            double a  = (lane < WPB) ? sm->red[lane][0] : 0.0;
            double bb = (lane < WPB) ? sm->red[lane][1] : 0.0;
            a = warpsumd(a); bb = warpsumd(bb);
            if (lane == 0) { g_asums[blockIdx.x][0] = a; g_asums[blockIdx.x][1] = bb; }
        }
        grid_barrier(epoch, tid);
        if (w == 0) {
            double s = 0, q = 0;
            for (int i = lane; i < WBLK; i += 32) { s += g_asums[i][0]; q += g_asums[i][1]; }
            s = warpsumd(s); q = warpsumd(q);
            if (lane == 0) {
                double mean = s / 65536.0, var = q / 65536.0 - mean * mean;
                float r = (float)(1.0 / sqrt(var + 1e-5));
                sm->bn[0] = r * ag;
                sm->bn[1] = ab - (float)mean * r * ag;
            }
        }
        __syncthreads();

        // ---------- straight-through select (argmax, first-index ties) ----------
        float score = (logit * sm->bn[0] + sm->bn[1]) * dfac;
        float best = score; int bj = lane;
        #pragma unroll
        for (int o = 16; o; o >>= 1) {
            float os = __shfl_down_sync(F, best, o);
            int   oj = __shfl_down_sync(F, bj, o);
            if (os > best || (os == best && oj < bj)) { best = os; bj = oj; }
        }
        bj = __shfl_sync(F, bj, 0);
        int gsel = __shfl_sync(F, myg, bj);
        float c1 = g_xw[(size_t)gsel * C + lane];
        float c2 = g_xw[(size_t)gsel * C + lane + 32];
        __syncwarp();
        sm->cur[w][lane]      = c1;
        sm->cur[w][lane + 32] = c2;
        out[(((size_t)(b * C + lane)) * CN + j) * CLEN + t]      = c1;
        out[(((size_t)(b * C + lane + 32)) * CN + j) * CLEN + t] = c2;
        fcur = gsel;
        __syncwarp();
    }
}

// ---------------- host ----------------
extern "C" void kernel_launch(void* const* d_in, const int* in_sizes, int n_in,
                              void* d_out, int out_size) {
    (void)in_sizes; (void)n_in; (void)out_size;
    const float* x       = (const float*)d_in[0];
    /* d_in[1] = xyz (unused by reference) */
    const int*   idx     = (const int*)d_in[2];
    const float* att_w   = (const float*)d_in[3];
    const float* agent_w = (const float*)d_in[4];
    const float* agent_g = (const float*)d_in[5];
    const float* agent_b = (const float*)d_in[6];
    const float* mom_w   = (const float*)d_in[7];
    const float* mom_g   = (const float*)d_in[8];
    const float* mom_b   = (const float*)d_in[9];
    float* out = (float*)d_out;

    cudaFuncSetAttribute(k_topk, cudaFuncAttributeMaxDynamicSharedMemorySize, NPTS * 8);
    cudaFuncSetAttribute(k_walk, cudaFuncAttributeMaxDynamicSharedMemorySize, (int)sizeof(SW));

    k_xw<<<BNB * 256, 256>>>(x, att_w);
    k_topk<<<BNB, 1024, NPTS * 8>>>();
    k_init<<<1, 128>>>();
    k_walk<<<WBLK, WTPB, sizeof(SW)>>>(idx, agent_w, agent_g, agent_b,
                                       mom_w, mom_g, mom_b, out);
}

// round 5
// speedup vs baseline: 1.2416x; 1.2416x over previous
#include <cuda_runtime.h>
#include <math.h>
#include <stdint.h>

#define BNB   8
#define C     64
#define NPTS  16384
#define KNBR  32
#define CN    256
#define CLEN  32
#define NCURVE (BNB*CN)     // 2048
#define WBLK  128           // walk grid blocks (<= #SMs, guaranteed co-resident)
#define WTPB  512
#define WPB   16            // warps (=curves) per block; WBLK*WPB == NCURVE
#define PVP   68            // padded pv row (stride 4 mod 32 banks -> conflict-free)

// ---------------- device scratch (no allocations allowed) ----------------
__device__ float  g_xw[(size_t)BNB*NPTS*C];   // point-major gated features [bn*n][c]
__device__ float  g_att[BNB*NPTS];
__device__ int    g_start[NCURVE];
__device__ float  g_mm[BNB*2*CN];             // raw momentum logits (for scrambled softmax)
__device__ double g_asums[WBLK][2];
__device__ double g_msums[WBLK][4];
__device__ int    g_flags[WBLK*32];           // one 128B line per flag

// ---------------- helpers ----------------
__device__ __forceinline__ float warpsum(float v) {
    #pragma unroll
    for (int o = 16; o; o >>= 1) v += __shfl_down_sync(0xFFFFFFFFu, v, o);
    return __shfl_sync(0xFFFFFFFFu, v, 0);
}
__device__ __forceinline__ double warpsumd(double v) {
    #pragma unroll
    for (int o = 16; o; o >>= 1) v += __shfl_down_sync(0xFFFFFFFFu, v, o);
    return __shfl_sync(0xFFFFFFFFu, v, 0);
}
__device__ __forceinline__ void st_release(int* p, int v) {
    asm volatile("st.release.gpu.global.s32 [%0], %1;" :: "l"(p), "r"(v) : "memory");
}
__device__ __forceinline__ int ld_acquire(int* p) {
    int v; asm volatile("ld.acquire.gpu.global.s32 %0, [%1];" : "=r"(v) : "l"(p) : "memory");
    return v;
}
// all-to-all grid barrier: one release-store per block, 128 acquire-pollers per block
__device__ __forceinline__ void gbar(int &epoch, int tid) {
    __syncthreads();
    ++epoch;
    if (tid == 0) st_release(&g_flags[blockIdx.x * 32], epoch);
    if (tid < WBLK) { while (ld_acquire(&g_flags[tid * 32]) < epoch) { } }
    __syncthreads();
}

// ---------------- kernel 1: x_att + transposed gated features ----------------
__global__ void k_xw(const float* __restrict__ x, const float* __restrict__ att_w) {
    __shared__ float sx[64][65];
    __shared__ float satt[64];
    __shared__ float sw[64];
    const int tid = threadIdx.x;
    const int b  = blockIdx.x >> 8;
    const int n0 = (blockIdx.x & 255) * 64;
    if (tid < 64) sw[tid] = att_w[tid];
    for (int i = tid; i < 64 * 64; i += 256) {
        int c = i >> 6, nn = i & 63;
        sx[c][nn] = x[((size_t)(b * C + c)) * NPTS + n0 + nn];
    }
    __syncthreads();
    if (tid < 64) {
        float s = 0.f;
        #pragma unroll
        for (int c = 0; c < 64; ++c) s += sx[c][tid] * sw[c];
        float a = 1.f / (1.f + expf(-s));
        satt[tid] = a;
        g_att[b * NPTS + n0 + tid] = a;
    }
    __syncthreads();
    for (int i = tid; i < 64 * 64; i += 256) {
        int nn = i >> 6, c = i & 63;
        g_xw[((size_t)(b * NPTS + n0 + nn)) * C + c] = sx[c][nn] * satt[nn];
    }
}

// -------- kernel 2: exact sorted top-256 per batch (chunk sort + max tournament) ----
__global__ void k_topk() {
    extern __shared__ unsigned long long sk[];
    const int tid = threadIdx.x;
    const int b = blockIdx.x;
    const int T = 1024;
    for (int i = tid; i < NPTS; i += T) {
        unsigned u = __float_as_uint(g_att[b * NPTS + i]);
        u = (u & 0x80000000u) ? ~u : (u | 0x80000000u);   // order-preserving map
        sk[i] = ((unsigned long long)u << 32) | (unsigned)(NPTS - 1 - i);
    }
    __syncthreads();
    // stage 1: bitonic-sort each 256-chunk; chunk c ascending iff c even
    for (int k = 2; k <= 256; k <<= 1) {
        for (int j = k >> 1; j > 0; j >>= 1) {
            for (int i = tid; i < NPTS; i += T) {
                int ixj = i ^ j;
                if (ixj > i) {
                    bool up = ((i & k) == 0);
                    unsigned long long a = sk[i], c = sk[ixj];
                    if ((a > c) == up) { sk[i] = c; sk[ixj] = a; }
                }
            }
            __syncthreads();
        }
    }
    // stage 2: tournament. top-256 of (asc chunk, desc chunk) = elementwise max (bitonic),
    // then an 8-pass bitonic merge re-sorts each winner chunk (asc iff even).
    int S = NPTS;
    while (S > 256) {
        int half = S >> 1;
        unsigned long long v[8];
        int cnt = 0;
        for (int i = tid; i < half; i += T) {
            int p = i >> 8, o = i & 255;
            unsigned long long a = sk[(2 * p) * 256 + o];
            unsigned long long c = sk[(2 * p + 1) * 256 + o];
            v[cnt++] = a > c ? a : c;
        }
        __syncthreads();
        cnt = 0;
        for (int i = tid; i < half; i += T) sk[i] = v[cnt++];
        __syncthreads();
        for (int j = 128; j > 0; j >>= 1) {
            for (int i = tid; i < half; i += T) {
                int ixj = i ^ j;
                if (ixj > i) {
                    bool up = ((i & 256) == 0);
                    unsigned long long a = sk[i], c = sk[ixj];
                    if ((a > c) == up) { sk[i] = c; sk[ixj] = a; }
                }
            }
            __syncthreads();
        }
        S = half;
    }
    if (tid < CN) {
        unsigned long long kk = sk[255 - tid];   // rank tid (desc, ties -> min idx)
        g_start[b * CN + tid] = NPTS - 1 - (int)(unsigned)(kk & 0xFFFFFFFFull);
    }
}

// ---------------- kernel 3: reset barrier state ----------------
__global__ void k_init() {
    for (int i = threadIdx.x; i < WBLK * 32; i += blockDim.x) g_flags[i] = 0;
}

// ---------------- kernel 4: persistent curve walk ----------------
struct SW {
    float  pv[WPB][KNBR][PVP];   // neighbor rows, channel-linear [0..63]
    float  pre[WPB][C];
    float  cur[WPB][C];
    float  aw[2 * C];
    float  mw[4 * C];
    double red[WPB][4];
    float  bn[4];
};

__global__ void __launch_bounds__(WTPB, 1) k_walk(
    const int* __restrict__ idx,
    const float* __restrict__ agent_w,
    const float* __restrict__ agent_gp, const float* __restrict__ agent_bp,
    const float* __restrict__ mom_w,
    const float* __restrict__ mom_gp, const float* __restrict__ mom_bp,
    float* __restrict__ out)
{
    extern __shared__ char smraw[];
    SW* sm = (SW*)smraw;
    const unsigned F = 0xFFFFFFFFu;
    const int tid = threadIdx.x;
    const int w = tid >> 5;
    const int lane = tid & 31;

    for (int i = tid; i < 2 * C; i += WTPB) sm->aw[i] = agent_w[i];
    for (int i = tid; i < 4 * C; i += WTPB) sm->mw[i] = mom_w[i];
    __syncthreads();
    const float ag = agent_gp[0], ab = agent_bp[0];
    const float mg0 = mom_gp[0], mg1 = mom_gp[1], mb0 = mom_bp[0], mb1 = mom_bp[1];

    const int cid = blockIdx.x * WPB + w;   // curve id 0..2047
    const int b = cid >> 8;
    const int j = cid & 255;
    int epoch = 0;

    int fcur = b * NPTS + g_start[cid];
    float pre1 = g_xw[(size_t)fcur * C + lane];
    float pre2 = g_xw[(size_t)fcur * C + lane + 32];
    float cur1 = 0.f, cur2 = 0.f;

    const int q  = lane & 7;     // 16B piece within a 128B line
    const int rg = lane >> 3;    // row-group 0..3

    for (int t = 0; t < CLEN; ++t) {
        const bool useD = (t > 0);

        // ---- A: coalesced gather of 32 neighbor rows into smem (overlaps barrier1) ----
        int myg = b * NPTS + idx[(size_t)fcur * KNBR + lane];
        #pragma unroll
        for (int p = 0; p < 8; ++p) {
            int row = p * 4 + rg;
            int g = __shfl_sync(F, myg, row);
            const float4* src = (const float4*)&g_xw[(size_t)g * C];
            float4 v0 = src[q];
            float4 v1 = src[8 + q];
            *(float4*)&sm->pv[w][row][q * 4]      = v0;
            *(float4*)&sm->pv[w][row][32 + q * 4] = v1;
        }

        // ---- B: momentum logits + global BN (steps >= 1) ----
        if (useD) {
            float m0 = cur1 * sm->mw[lane]       + cur2 * sm->mw[32 + lane]
                     + pre1 * sm->mw[64 + lane]  + pre2 * sm->mw[96 + lane];
            float m1 = cur1 * sm->mw[128 + lane] + cur2 * sm->mw[160 + lane]
                     + pre1 * sm->mw[192 + lane] + pre2 * sm->mw[224 + lane];
            m0 = warpsum(m0); m1 = warpsum(m1);
            if (lane == 0) {
                g_mm[b * 512 + j]       = m0;
                g_mm[b * 512 + 256 + j] = m1;
                sm->red[w][0] = (double)m0; sm->red[w][1] = (double)m0 * m0;
                sm->red[w][2] = (double)m1; sm->red[w][3] = (double)m1 * m1;
            }
            __syncthreads();
            if (w == 0) {
                double r0 = (lane < WPB) ? sm->red[lane][0] : 0.0;
                double r1 = (lane < WPB) ? sm->red[lane][1] : 0.0;
                double r2 = (lane < WPB) ? sm->red[lane][2] : 0.0;
                double r3 = (lane < WPB) ? sm->red[lane][3] : 0.0;
                r0 = warpsumd(r0); r1 = warpsumd(r1); r2 = warpsumd(r2); r3 = warpsumd(r3);
                if (lane == 0) {
                    g_msums[blockIdx.x][0] = r0; g_msums[blockIdx.x][1] = r1;
                    g_msums[blockIdx.x][2] = r2; g_msums[blockIdx.x][3] = r3;
                }
            }
            gbar(epoch, tid);
            if (w == 0) {
                double s0 = 0, q0 = 0, s1 = 0, q1 = 0;
                for (int i = lane; i < WBLK; i += 32) {
                    s0 += g_msums[i][0]; q0 += g_msums[i][1];
                    s1 += g_msums[i][2]; q1 += g_msums[i][3];
                }
                s0 = warpsumd(s0); q0 = warpsumd(q0); s1 = warpsumd(s1); q1 = warpsumd(q1);
                if (lane == 0) {
                    double mean0 = s0 / 2048.0, var0 = q0 / 2048.0 - mean0 * mean0;
                    double mean1 = s1 / 2048.0, var1 = q1 / 2048.0 - mean1 * mean1;
                    float r0f = (float)(1.0 / sqrt(var0 + 1e-5));
                    float r1f = (float)(1.0 / sqrt(var1 + 1e-5));
                    sm->bn[0] = r0f * mg0; sm->bn[1] = mb0 - (float)mean0 * r0f * mg0;
                    sm->bn[2] = r1f * mg1; sm->bn[3] = mb1 - (float)mean1 * r1f * mg1;
                }
            }
            __syncthreads();
            // scrambled attention weights (torch .view reshape semantics)
            float att = 0.f;
            if (lane < 2) {
                int f  = 2 * j + lane;
                int ch = f >> 8, jj = f & 255;
                float v0 = g_mm[b * 512 + jj]       * sm->bn[0] + sm->bn[1];
                float v1 = g_mm[b * 512 + 256 + jj] * sm->bn[2] + sm->bn[3];
                float mx = fmaxf(v0, v1);
                float e0 = expf(v0 - mx), e1 = expf(v1 - mx);
                att = ((ch == 0) ? e0 : e1) / (e0 + e1);
            }
            float att0 = __shfl_sync(F, att, 0);
            float att1 = __shfl_sync(F, att, 1);
            pre1 = cur1 * att0 + pre1 * att1;
            pre2 = cur2 * att0 + pre2 * att1;
            sm->pre[w][lane]      = pre1;
            sm->pre[w][lane + 32] = pre2;
            __syncwarp();
        }

        // ---- D: per-neighbor dot products from smem (lane owns neighbor `lane`) ----
        float pd = warpsum(pre1 * sm->aw[C + lane] + pre2 * sm->aw[C + lane + 32]);
        float anorm = 0.f;
        if (useD) {
            float a1 = cur1 - pre1, a2 = cur2 - pre2;
            anorm = sqrtf(warpsum(a1 * a1 + a2 * a2));
        }
        __syncwarp();   // pv stores visible within warp (t==0 path has no barrier)
        float pvdot = 0.f, dotv = 0.f, n2 = 0.f;
        #pragma unroll
        for (int cc = 0; cc < 16; ++cc) {
            float4 pvv = *(const float4*)&sm->pv[w][lane][cc * 4];
            float4 awv = *(const float4*)&sm->aw[cc * 4];
            pvdot += pvv.x * awv.x; pvdot += pvv.y * awv.y;
            pvdot += pvv.z * awv.z; pvdot += pvv.w * awv.w;
            if (useD) {
                float4 cuv = *(const float4*)&sm->cur[w][cc * 4];
                float4 prv = *(const float4*)&sm->pre[w][cc * 4];
                float dx;
                dx = pvv.x - cuv.x; dotv += (cuv.x - prv.x) * dx; n2 += dx * dx;
                dx = pvv.y - cuv.y; dotv += (cuv.y - prv.y) * dx; n2 += dx * dx;
                dx = pvv.z - cuv.z; dotv += (cuv.z - prv.z) * dx; n2 += dx * dx;
                dx = pvv.w - cuv.w; dotv += (cuv.w - prv.w) * dx; n2 += dx * dx;
            }
        }
        float raw = pvdot + pd;
        float dfac = 1.f;
        if (useD) {
            float div = fmaxf(anorm * sqrtf(n2), 1e-8f);
            dfac = fminf(fmaxf(1.f + dotv / div, 0.f), 1.f);
        }

        // ---- E: global BN over all 65536 logits ----
        double ls = warpsumd((double)raw);
        double l2 = warpsumd((double)raw * (double)raw);
        if (lane == 0) { sm->red[w][0] = ls; sm->red[w][1] = l2; }
        __syncthreads();
        if (w == 0) {
            double a  = (lane < WPB) ? sm->red[lane][0] : 0.0;
            double bb = (lane < WPB) ? sm->red[lane][1] : 0.0;
            a = warpsumd(a); bb = warpsumd(bb);
            if (lane == 0) { g_asums[blockIdx.x][0] = a; g_asums[blockIdx.x][1] = bb; }
        }
        gbar(epoch, tid);
        if (w == 0) {
            double s = 0, qq = 0;
            for (int i = lane; i < WBLK; i += 32) { s += g_asums[i][0]; qq += g_asums[i][1]; }
            s = warpsumd(s); qq = warpsumd(qq);
            if (lane == 0) {
                double mean = s / 65536.0, var = qq / 65536.0 - mean * mean;
                float r = (float)(1.0 / sqrt(var + 1e-5));
                sm->bn[0] = r * ag;
                sm->bn[1] = ab - (float)mean * r * ag;
            }
        }
        __syncthreads();

        // ---- F: straight-through select (argmax, first-index ties) ----
        float score = (raw * sm->bn[0] + sm->bn[1]) * dfac;
        float best = score; int bj = lane;
        #pragma unroll
        for (int o = 16; o; o >>= 1) {
            float os = __shfl_down_sync(F, best, o);
            int   oj = __shfl_down_sync(F, bj, o);
            if (os > best || (os == best && oj < bj)) { best = os; bj = oj; }
        }
        bj = __shfl_sync(F, bj, 0);
        int gsel = __shfl_sync(F, myg, bj);
        float c1 = sm->pv[w][bj][lane];
        float c2 = sm->pv[w][bj][32 + lane];
        cur1 = c1; cur2 = c2;
        sm->cur[w][lane]      = c1;
        sm->cur[w][lane + 32] = c2;
        out[(((size_t)(b * C + lane)) * CN + j) * CLEN + t]      = c1;
        out[(((size_t)(b * C + lane + 32)) * CN + j) * CLEN + t] = c2;
        fcur = gsel;
        __syncwarp();
    }
}

// ---------------- host ----------------
extern "C" void kernel_launch(void* const* d_in, const int* in_sizes, int n_in,
                              void* d_out, int out_size) {
    (void)in_sizes; (void)n_in; (void)out_size;
    const float* x       = (const float*)d_in[0];
    /* d_in[1] = xyz (unused by reference) */
    const int*   idx     = (const int*)d_in[2];
    const float* att_w   = (const float*)d_in[3];
    const float* agent_w = (const float*)d_in[4];
    const float* agent_g = (const float*)d_in[5];
    const float* agent_b = (const float*)d_in[6];
    const float* mom_w   = (const float*)d_in[7];
    const float* mom_g   = (const float*)d_in[8];
    const float* mom_b   = (const float*)d_in[9];
    float* out = (float*)d_out;

    cudaFuncSetAttribute(k_topk, cudaFuncAttributeMaxDynamicSharedMemorySize, NPTS * 8);
    cudaFuncSetAttribute(k_walk, cudaFuncAttributeMaxDynamicSharedMemorySize, (int)sizeof(SW));

    k_xw<<<BNB * 256, 256>>>(x, att_w);
    k_topk<<<BNB, 1024, NPTS * 8>>>();
    k_init<<<1, 512>>>();
    k_walk<<<WBLK, WTPB, sizeof(SW)>>>(idx, agent_w, agent_g, agent_b,
                                       mom_w, mom_g, mom_b, out);
}

// round 6
// speedup vs baseline: 1.8996x; 1.5299x over previous
#include <cuda_runtime.h>
#include <math.h>
#include <stdint.h>

#define BNB   8
#define C     64
#define NPTS  16384
#define KNBR  32
#define CN    256
#define CLEN  32
#define NCURVE (BNB*CN)     // 2048
#define WBLK  128           // walk grid blocks (co-resident on 148 SMs)
#define WTPB  512
#define WPB   16            // warps (=curves) per block; WBLK*WPB == NCURVE
#define PVP   68            // padded pv row

// ---------------- device scratch (no allocations allowed) ----------------
__device__ float  g_xw[(size_t)BNB*NPTS*C];   // point-major gated features [bn*n][c]
__device__ float  g_att[BNB*NPTS];
__device__ int    g_start[NCURVE];
__device__ float  g_mm[BNB*2*CN];             // raw momentum logits (for scrambled softmax)
__device__ float  g_curve[NCURVE][CLEN][C];   // curve-major staging for output
__device__ double g_asums[WBLK][2];
__device__ double g_msums[WBLK][4];
__device__ int    g_flags[WBLK*32];           // one 128B line per flag

// ---------------- helpers ----------------
__device__ __forceinline__ float warpsum(float v) {
    #pragma unroll
    for (int o = 16; o; o >>= 1) v += __shfl_down_sync(0xFFFFFFFFu, v, o);
    return __shfl_sync(0xFFFFFFFFu, v, 0);
}
__device__ __forceinline__ double warpsumd(double v) {
    #pragma unroll
    for (int o = 16; o; o >>= 1) v += __shfl_down_sync(0xFFFFFFFFu, v, o);
    return __shfl_sync(0xFFFFFFFFu, v, 0);
}
__device__ __forceinline__ void st_release(int* p, int v) {
    asm volatile("st.release.gpu.global.s32 [%0], %1;" :: "l"(p), "r"(v) : "memory");
}
__device__ __forceinline__ int ld_acquire(int* p) {
    int v; asm volatile("ld.acquire.gpu.global.s32 %0, [%1];" : "=r"(v) : "l"(p) : "memory");
    return v;
}

// ---------------- kernel 1: x_att + transposed gated features ----------------
__global__ void k_xw(const float* __restrict__ x, const float* __restrict__ att_w) {
    __shared__ float sx[64][65];
    __shared__ float satt[64];
    __shared__ float sw[64];
    const int tid = threadIdx.x;
    const int b  = blockIdx.x >> 8;
    const int n0 = (blockIdx.x & 255) * 64;
    if (tid < 64) sw[tid] = att_w[tid];
    for (int i = tid; i < 64 * 64; i += 256) {
        int c = i >> 6, nn = i & 63;
        sx[c][nn] = x[((size_t)(b * C + c)) * NPTS + n0 + nn];
    }
    __syncthreads();
    if (tid < 64) {
        float s = 0.f;
        #pragma unroll
        for (int c = 0; c < 64; ++c) s += sx[c][tid] * sw[c];
        float a = 1.f / (1.f + expf(-s));
        satt[tid] = a;
        g_att[b * NPTS + n0 + tid] = a;
    }
    __syncthreads();
    for (int i = tid; i < 64 * 64; i += 256) {
        int nn = i >> 6, c = i & 63;
        g_xw[((size_t)(b * NPTS + n0 + nn)) * C + c] = sx[c][nn] * satt[nn];
    }
}

// -------- kernel 2: exact sorted top-256 per batch (chunk sort + max tournament) ----
__global__ void k_topk() {
    extern __shared__ unsigned long long sk[];
    const int tid = threadIdx.x;
    const int b = blockIdx.x;
    const int T = 1024;
    for (int i = tid; i < NPTS; i += T) {
        unsigned u = __float_as_uint(g_att[b * NPTS + i]);
        u = (u & 0x80000000u) ? ~u : (u | 0x80000000u);   // order-preserving map
        sk[i] = ((unsigned long long)u << 32) | (unsigned)(NPTS - 1 - i);
    }
    __syncthreads();
    for (int k = 2; k <= 256; k <<= 1) {
        for (int j = k >> 1; j > 0; j >>= 1) {
            for (int i = tid; i < NPTS; i += T) {
                int ixj = i ^ j;
                if (ixj > i) {
                    bool up = ((i & k) == 0);
                    unsigned long long a = sk[i], c = sk[ixj];
                    if ((a > c) == up) { sk[i] = c; sk[ixj] = a; }
                }
            }
            __syncthreads();
        }
    }
    int S = NPTS;
    while (S > 256) {
        int half = S >> 1;
        unsigned long long v[8];
        int cnt = 0;
        for (int i = tid; i < half; i += T) {
            int p = i >> 8, o = i & 255;
            unsigned long long a = sk[(2 * p) * 256 + o];
            unsigned long long c = sk[(2 * p + 1) * 256 + o];
            v[cnt++] = a > c ? a : c;
        }
        __syncthreads();
        cnt = 0;
        for (int i = tid; i < half; i += T) sk[i] = v[cnt++];
        __syncthreads();
        for (int j = 128; j > 0; j >>= 1) {
            for (int i = tid; i < half; i += T) {
                int ixj = i ^ j;
                if (ixj > i) {
                    bool up = ((i & 256) == 0);
                    unsigned long long a = sk[i], c = sk[ixj];
                    if ((a > c) == up) { sk[i] = c; sk[ixj] = a; }
                }
            }
            __syncthreads();
        }
        S = half;
    }
    if (tid < CN) {
        unsigned long long kk = sk[255 - tid];
        g_start[b * CN + tid] = NPTS - 1 - (int)(unsigned)(kk & 0xFFFFFFFFull);
    }
}

// ---------------- kernel 3: reset barrier state ----------------
__global__ void k_init() {
    for (int i = threadIdx.x; i < WBLK * 32; i += blockDim.x) g_flags[i] = 0;
}

// ---------------- kernel 4: persistent curve walk ----------------
struct SW {
    float  pv[WPB][KNBR][PVP];   // neighbor rows, channel-linear [0..63]
    float  pre[WPB][C];
    float  cur[WPB][C];
    float  aw[2 * C];
    float  mw[4 * C];
    double red[WPB][4];
    float  bn[4];
};

__global__ void __launch_bounds__(WTPB, 1) k_walk(
    const int* __restrict__ idx,
    const float* __restrict__ agent_w,
    const float* __restrict__ agent_gp, const float* __restrict__ agent_bp,
    const float* __restrict__ mom_w,
    const float* __restrict__ mom_gp, const float* __restrict__ mom_bp,
    float* __restrict__ out)
{
    extern __shared__ char smraw[];
    SW* sm = (SW*)smraw;
    const unsigned F = 0xFFFFFFFFu;
    const int tid = threadIdx.x;
    const int w = tid >> 5;
    const int lane = tid & 31;

    for (int i = tid; i < 2 * C; i += WTPB) sm->aw[i] = agent_w[i];
    for (int i = tid; i < 4 * C; i += WTPB) sm->mw[i] = mom_w[i];
    __syncthreads();
    const float ag = agent_gp[0], ab = agent_bp[0];
    const float mg0 = mom_gp[0], mg1 = mom_gp[1], mb0 = mom_bp[0], mb1 = mom_bp[1];

    const int cid = blockIdx.x * WPB + w;   // curve id 0..2047
    const int b = cid >> 8;
    const int j = cid & 255;
    int epoch = 0;

    int fcur = b * NPTS + g_start[cid];
    float pre1 = g_xw[(size_t)fcur * C + lane];
    float pre2 = g_xw[(size_t)fcur * C + lane + 32];
    float cur1 = 0.f, cur2 = 0.f;

    const int q  = lane & 7;     // 16B piece within a 128B line
    const int rg = lane >> 3;    // row-group 0..3

    for (int t = 0; t < CLEN; ++t) {
        const bool useD = (t > 0);
        int myg = b * NPTS + idx[(size_t)fcur * KNBR + lane];  // issue idx load early

        if (useD) {
            // ---- momentum logits + arrive for global reduce #1 ----
            float m0 = cur1 * sm->mw[lane]       + cur2 * sm->mw[32 + lane]
                     + pre1 * sm->mw[64 + lane]  + pre2 * sm->mw[96 + lane];
            float m1 = cur1 * sm->mw[128 + lane] + cur2 * sm->mw[160 + lane]
                     + pre1 * sm->mw[192 + lane] + pre2 * sm->mw[224 + lane];
            m0 = warpsum(m0); m1 = warpsum(m1);
            if (lane == 0) {
                g_mm[b * 512 + j]       = m0;
                g_mm[b * 512 + 256 + j] = m1;
                sm->red[w][0] = (double)m0; sm->red[w][1] = (double)m0 * m0;
                sm->red[w][2] = (double)m1; sm->red[w][3] = (double)m1 * m1;
            }
            __syncthreads();
            if (w == 0) {
                double r0 = (lane < WPB) ? sm->red[lane][0] : 0.0;
                double r1 = (lane < WPB) ? sm->red[lane][1] : 0.0;
                double r2 = (lane < WPB) ? sm->red[lane][2] : 0.0;
                double r3 = (lane < WPB) ? sm->red[lane][3] : 0.0;
                r0 = warpsumd(r0); r1 = warpsumd(r1); r2 = warpsumd(r2); r3 = warpsumd(r3);
                if (lane == 0) {
                    g_msums[blockIdx.x][0] = r0; g_msums[blockIdx.x][1] = r1;
                    g_msums[blockIdx.x][2] = r2; g_msums[blockIdx.x][3] = r3;
                }
            }
            __syncthreads();
            ++epoch;
            if (tid == 0) st_release(&g_flags[blockIdx.x * 32], epoch);
        }

        // ---- gather 32 neighbor rows into smem: hidden under barrier #1 wait ----
        #pragma unroll
        for (int p = 0; p < 8; ++p) {
            int row = p * 4 + rg;
            int g = __shfl_sync(F, myg, row);
            const float4* src = (const float4*)&g_xw[(size_t)g * C];
            float4 v0 = src[q];
            float4 v1 = src[8 + q];
            *(float4*)&sm->pv[w][row][q * 4]      = v0;
            *(float4*)&sm->pv[w][row][32 + q * 4] = v1;
        }

        if (useD) {
            // ---- complete barrier #1, compute momentum BN, blend pre ----
            if (tid < WBLK) { while (ld_acquire(&g_flags[tid * 32]) < epoch) { } }
            __syncthreads();
            if (w == 0) {
                double s0 = 0, q0 = 0, s1 = 0, q1 = 0;
                for (int i = lane; i < WBLK; i += 32) {
                    s0 += g_msums[i][0]; q0 += g_msums[i][1];
                    s1 += g_msums[i][2]; q1 += g_msums[i][3];
                }
                s0 = warpsumd(s0); q0 = warpsumd(q0); s1 = warpsumd(s1); q1 = warpsumd(q1);
                if (lane == 0) {
                    double mean0 = s0 / 2048.0, var0 = q0 / 2048.0 - mean0 * mean0;
                    double mean1 = s1 / 2048.0, var1 = q1 / 2048.0 - mean1 * mean1;
                    float r0f = (float)(1.0 / sqrt(var0 + 1e-5));
                    float r1f = (float)(1.0 / sqrt(var1 + 1e-5));
                    sm->bn[0] = r0f * mg0; sm->bn[1] = mb0 - (float)mean0 * r0f * mg0;
                    sm->bn[2] = r1f * mg1; sm->bn[3] = mb1 - (float)mean1 * r1f * mg1;
                }
            }
            __syncthreads();
            // scrambled attention weights (torch .view reshape semantics)
            float att = 0.f;
            if (lane < 2) {
                int f  = 2 * j + lane;
                int ch = f >> 8, jj = f & 255;
                float v0 = g_mm[b * 512 + jj]       * sm->bn[0] + sm->bn[1];
                float v1 = g_mm[b * 512 + 256 + jj] * sm->bn[2] + sm->bn[3];
                float mx = fmaxf(v0, v1);
                float e0 = expf(v0 - mx), e1 = expf(v1 - mx);
                att = ((ch == 0) ? e0 : e1) / (e0 + e1);
            }
            float att0 = __shfl_sync(F, att, 0);
            float att1 = __shfl_sync(F, att, 1);
            pre1 = cur1 * att0 + pre1 * att1;
            pre2 = cur2 * att0 + pre2 * att1;
            sm->pre[w][lane]      = pre1;
            sm->pre[w][lane + 32] = pre2;
            __syncwarp();
        }

        // ---- per-neighbor dot products from smem (lane owns neighbor `lane`) ----
        float pd = warpsum(pre1 * sm->aw[C + lane] + pre2 * sm->aw[C + lane + 32]);
        float anorm = 0.f;
        if (useD) {
            float a1 = cur1 - pre1, a2 = cur2 - pre2;
            anorm = sqrtf(warpsum(a1 * a1 + a2 * a2));
        }
        __syncwarp();   // pv stores visible within warp (t==0 path has no barrier)
        float pvdot = 0.f, dotv = 0.f, n2 = 0.f;
        #pragma unroll
        for (int cc = 0; cc < 16; ++cc) {
            float4 pvv = *(const float4*)&sm->pv[w][lane][cc * 4];
            float4 awv = *(const float4*)&sm->aw[cc * 4];
            pvdot += pvv.x * awv.x; pvdot += pvv.y * awv.y;
            pvdot += pvv.z * awv.z; pvdot += pvv.w * awv.w;
            if (useD) {
                float4 cuv = *(const float4*)&sm->cur[w][cc * 4];
                float4 prv = *(const float4*)&sm->pre[w][cc * 4];
                float dx;
                dx = pvv.x - cuv.x; dotv += (cuv.x - prv.x) * dx; n2 += dx * dx;
                dx = pvv.y - cuv.y; dotv += (cuv.y - prv.y) * dx; n2 += dx * dx;
                dx = pvv.z - cuv.z; dotv += (cuv.z - prv.z) * dx; n2 += dx * dx;
                dx = pvv.w - cuv.w; dotv += (cuv.w - prv.w) * dx; n2 += dx * dx;
            }
        }
        float raw = pvdot + pd;
        float dfac = 1.f;
        if (useD) {
            float div = fmaxf(anorm * sqrtf(n2), 1e-8f);
            dfac = fminf(fmaxf(1.f + dotv / div, 0.f), 1.f);
        }

        // ---- global BN over all 65536 logits (reduce #2) ----
        double ls = warpsumd((double)raw);
        double l2 = warpsumd((double)raw * (double)raw);
        if (lane == 0) { sm->red[w][0] = ls; sm->red[w][1] = l2; }
        __syncthreads();
        if (w == 0) {
            double a  = (lane < WPB) ? sm->red[lane][0] : 0.0;
            double bb = (lane < WPB) ? sm->red[lane][1] : 0.0;
            a = warpsumd(a); bb = warpsumd(bb);
            if (lane == 0) { g_asums[blockIdx.x][0] = a; g_asums[blockIdx.x][1] = bb; }
        }
        __syncthreads();
        ++epoch;
        if (tid == 0) st_release(&g_flags[blockIdx.x * 32], epoch);
        if (tid < WBLK) { while (ld_acquire(&g_flags[tid * 32]) < epoch) { } }
        __syncthreads();
        if (w == 0) {
            double s = 0, qq = 0;
            for (int i = lane; i < WBLK; i += 32) { s += g_asums[i][0]; qq += g_asums[i][1]; }
            s = warpsumd(s); qq = warpsumd(qq);
            if (lane == 0) {
                double mean = s / 65536.0, var = qq / 65536.0 - mean * mean;
                float r = (float)(1.0 / sqrt(var + 1e-5));
                sm->bn[0] = r * ag;
                sm->bn[1] = ab - (float)mean * r * ag;
            }
        }
        __syncthreads();

        // ---- straight-through select (argmax, first-index ties) ----
        float score = (raw * sm->bn[0] + sm->bn[1]) * dfac;
        float best = score; int bj = lane;
        #pragma unroll
        for (int o = 16; o; o >>= 1) {
            float os = __shfl_down_sync(F, best, o);
            int   oj = __shfl_down_sync(F, bj, o);
            if (os > best || (os == best && oj < bj)) { best = os; bj = oj; }
        }
        bj = __shfl_sync(F, bj, 0);
        int gsel = __shfl_sync(F, myg, bj);
        float c1 = sm->pv[w][bj][lane];
        float c2 = sm->pv[w][bj][32 + lane];
        cur1 = c1; cur2 = c2;
        sm->cur[w][lane]      = c1;
        sm->cur[w][lane + 32] = c2;
        g_curve[cid][t][lane]      = c1;   // coalesced staging (2 lines per warp)
        g_curve[cid][t][lane + 32] = c2;
        fcur = gsel;
        __syncwarp();
    }

    // ---- epilogue: per-warp transpose of the curve tile, fully coalesced out ----
    __syncwarp();
    {
        // load [t=lane][c] rows into pv[w][lane][0..63]
        const float4* src = (const float4*)&g_curve[cid][lane][0];
        #pragma unroll
        for (int i = 0; i < 16; ++i) {
            float4 v = src[i];
            *(float4*)&sm->pv[w][lane][i * 4] = v;
        }
        __syncwarp();
        #pragma unroll
        for (int h = 0; h < 2; ++h) {
            int c = lane + h * 32;
            size_t obase = (((size_t)(b * C + c)) * CN + j) * CLEN;
            #pragma unroll
            for (int tc = 0; tc < 8; ++tc) {
                float4 v;
                v.x = sm->pv[w][tc * 4 + 0][c];
                v.y = sm->pv[w][tc * 4 + 1][c];
                v.z = sm->pv[w][tc * 4 + 2][c];
                v.w = sm->pv[w][tc * 4 + 3][c];
                *(float4*)&out[obase + tc * 4] = v;
            }
        }
    }
}

// ---------------- host ----------------
extern "C" void kernel_launch(void* const* d_in, const int* in_sizes, int n_in,
                              void* d_out, int out_size) {
    (void)in_sizes; (void)n_in; (void)out_size;
    const float* x       = (const float*)d_in[0];
    /* d_in[1] = xyz (unused by reference) */
    const int*   idx     = (const int*)d_in[2];
    const float* att_w   = (const float*)d_in[3];
    const float* agent_w = (const float*)d_in[4];
    const float* agent_g = (const float*)d_in[5];
    const float* agent_b = (const float*)d_in[6];
    const float* mom_w   = (const float*)d_in[7];
    const float* mom_g   = (const float*)d_in[8];
    const float* mom_b   = (const float*)d_in[9];
    float* out = (float*)d_out;

    cudaFuncSetAttribute(k_topk, cudaFuncAttributeMaxDynamicSharedMemorySize, NPTS * 8);
    cudaFuncSetAttribute(k_walk, cudaFuncAttributeMaxDynamicSharedMemorySize, (int)sizeof(SW));

    k_xw<<<BNB * 256, 256>>>(x, att_w);
    k_topk<<<BNB, 1024, NPTS * 8>>>();
    k_init<<<1, 512>>>();
    k_walk<<<WBLK, WTPB, sizeof(SW)>>>(idx, agent_w, agent_g, agent_b,
                                       mom_w, mom_g, mom_b, out);
}

// round 11
// speedup vs baseline: 1.9885x; 1.0468x over previous
#include <cuda_runtime.h>
#include <math.h>
#include <stdint.h>

#define BNB   8
#define C     64
#define NPTS  16384
#define KNBR  32
#define CN    256
#define CLEN  32
#define NCURVE (BNB*CN)     // 2048
#define WBLK  128           // walk grid blocks (co-resident on 148 SMs)
#define WTPB  512
#define WPB   16            // warps (=curves) per block
#define PVP   68            // padded pv row

#define SCALE_S 17179869184.0      // 2^34 for sums
#define SCALE_Q 1073741824.0       // 2^30 for sums of squares

// ---------------- device scratch (no allocations allowed) ----------------
__device__ float  g_xw[(size_t)BNB*NPTS*C];   // point-major gated features [bn*n][c]
__device__ float  g_att[BNB*NPTS];
__device__ int    g_start[NCURVE];
__device__ float  g_mm[BNB*2*CN];             // raw momentum logits (scrambled softmax)
__device__ float  g_curve[NCURVE][CLEN][C];   // curve-major staging for output
// 64 reduction slots: agent(t)->slot 2t, momentum(t)->slot 2t-1
__device__ unsigned long long g_rsum[64][4][32];  // entry stride 256B (slice spread)
__device__ unsigned int       g_rcnt[64][64];     // cnt at [s][0], 256B stride
__device__ float              g_rcoef[64][32];    // published BN coefs (one line)
__device__ int                g_rflag[64][32];    // publish flag (one line)

// ---------------- helpers ----------------
__device__ __forceinline__ float warpsum(float v) {
    #pragma unroll
    for (int o = 16; o; o >>= 1) v += __shfl_down_sync(0xFFFFFFFFu, v, o);
    return __shfl_sync(0xFFFFFFFFu, v, 0);
}
__device__ __forceinline__ void warpsum3(float& a, float& b, float& c) {
    #pragma unroll
    for (int o = 16; o; o >>= 1) {
        a += __shfl_down_sync(0xFFFFFFFFu, a, o);
        b += __shfl_down_sync(0xFFFFFFFFu, b, o);
        c += __shfl_down_sync(0xFFFFFFFFu, c, o);
    }
    a = __shfl_sync(0xFFFFFFFFu, a, 0);
    b = __shfl_sync(0xFFFFFFFFu, b, 0);
    c = __shfl_sync(0xFFFFFFFFu, c, 0);
}
__device__ __forceinline__ double warpsumd(double v) {
    #pragma unroll
    for (int o = 16; o; o >>= 1) v += __shfl_down_sync(0xFFFFFFFFu, v, o);
    return __shfl_sync(0xFFFFFFFFu, v, 0);
}
__device__ __forceinline__ void stg_rel_s32(int* p, int v) {
    asm volatile("st.release.gpu.global.s32 [%0], %1;" :: "l"(p), "r"(v) : "memory");
}
__device__ __forceinline__ int ldg_acq_s32(int* p) {
    int v; asm volatile("ld.acquire.gpu.global.s32 %0, [%1];" : "=r"(v) : "l"(p) : "memory");
    return v;
}
__device__ __forceinline__ float ldg_rlx_f32(const float* p) {
    float v; asm volatile("ld.relaxed.gpu.global.f32 %0, [%1];" : "=f"(v) : "l"(p) : "memory");
    return v;
}
__device__ __forceinline__ void stg_rlx_f32(float* p, float v) {
    asm volatile("st.relaxed.gpu.global.f32 [%0], %1;" :: "l"(p), "f"(v) : "memory");
}
__device__ __forceinline__ unsigned long long ldg_rlx_u64(const unsigned long long* p) {
    unsigned long long v;
    asm volatile("ld.relaxed.gpu.global.u64 %0, [%1];" : "=l"(v) : "l"(p) : "memory");
    return v;
}

// ---------------- kernel 1: x_att + transposed gated features (+ slot zeroing) ----
__global__ void k_xw(const float* __restrict__ x, const float* __restrict__ att_w) {
    __shared__ float sx[64][65];
    __shared__ float satt[64];
    __shared__ float sw[64];
    const int tid = threadIdx.x;
    const int b  = blockIdx.x >> 8;
    const int n0 = (blockIdx.x & 255) * 64;
    if (blockIdx.x < 64) {           // reset reduction slots for this launch
        int s = blockIdx.x;
        if (tid < 4)       g_rsum[s][tid][0] = 0ull;
        else if (tid == 4) g_rcnt[s][0] = 0u;
        else if (tid == 5) g_rflag[s][0] = 0;
    }
    if (tid < 64) sw[tid] = att_w[tid];
    for (int i = tid; i < 64 * 64; i += 256) {
        int c = i >> 6, nn = i & 63;
        sx[c][nn] = x[((size_t)(b * C + c)) * NPTS + n0 + nn];
    }
    __syncthreads();
    if (tid < 64) {
        float s = 0.f;
        #pragma unroll
        for (int c = 0; c < 64; ++c) s += sx[c][tid] * sw[c];
        float a = 1.f / (1.f + expf(-s));
        satt[tid] = a;
        g_att[b * NPTS + n0 + tid] = a;
    }
    __syncthreads();
    for (int i = tid; i < 64 * 64; i += 256) {
        int nn = i >> 6, c = i & 63;
        g_xw[((size_t)(b * NPTS + n0 + nn)) * C + c] = sx[c][nn] * satt[nn];
    }
}

// -------- kernel 2: exact sorted top-256 per batch (chunk sort + max tournament) ----
__global__ void k_topk() {
    extern __shared__ unsigned long long sk[];
    const int tid = threadIdx.x;
    const int b = blockIdx.x;
    const int T = 1024;
    for (int i = tid; i < NPTS; i += T) {
        unsigned u = __float_as_uint(g_att[b * NPTS + i]);
        u = (u & 0x80000000u) ? ~u : (u | 0x80000000u);
        sk[i] = ((unsigned long long)u << 32) | (unsigned)(NPTS - 1 - i);
    }
    __syncthreads();
    for (int k = 2; k <= 256; k <<= 1) {
        for (int j = k >> 1; j > 0; j >>= 1) {
            for (int i = tid; i < NPTS; i += T) {
                int ixj = i ^ j;
                if (ixj > i) {
                    bool up = ((i & k) == 0);
                    unsigned long long a = sk[i], c = sk[ixj];
                    if ((a > c) == up) { sk[i] = c; sk[ixj] = a; }
                }
            }
            __syncthreads();
        }
    }
    int S = NPTS;
    while (S > 256) {
        int half = S >> 1;
        unsigned long long v[8];
        int cnt = 0;
        for (int i = tid; i < half; i += T) {
            int p = i >> 8, o = i & 255;
            unsigned long long a = sk[(2 * p) * 256 + o];
            unsigned long long c = sk[(2 * p + 1) * 256 + o];
            v[cnt++] = a > c ? a : c;
        }
        __syncthreads();
        cnt = 0;
        for (int i = tid; i < half; i += T) sk[i] = v[cnt++];
        __syncthreads();
        for (int j = 128; j > 0; j >>= 1) {
            for (int i = tid; i < half; i += T) {
                int ixj = i ^ j;
                if (ixj > i) {
                    bool up = ((i & 256) == 0);
                    unsigned long long a = sk[i], c = sk[ixj];
                    if ((a > c) == up) { sk[i] = c; sk[ixj] = a; }
                }
            }
            __syncthreads();
        }
        S = half;
    }
    if (tid < CN) {
        unsigned long long kk = sk[255 - tid];
        g_start[b * CN + tid] = NPTS - 1 - (int)(unsigned)(kk & 0xFFFFFFFFull);
    }
}

// ---------------- kernel 3: persistent curve walk ----------------
struct SW {
    float  pv[WPB][KNBR][PVP];
    float  pre[WPB][C];
    float  cur[WPB][C];
    float  aw[2 * C];
    float  mw[4 * C];
    double red[WPB][4];
    float  bn[8];        // [0..3] momentum coefs, [4..5] agent coefs
};

__global__ void __launch_bounds__(WTPB, 1) k_walk(
    const int* __restrict__ idx,
    const float* __restrict__ agent_w,
    const float* __restrict__ agent_gp, const float* __restrict__ agent_bp,
    const float* __restrict__ mom_w,
    const float* __restrict__ mom_gp, const float* __restrict__ mom_bp,
    float* __restrict__ out)
{
    extern __shared__ char smraw[];
    SW* sm = (SW*)smraw;
    const unsigned F = 0xFFFFFFFFu;
    const int tid = threadIdx.x;
    const int w = tid >> 5;
    const int lane = tid & 31;

    for (int i = tid; i < 2 * C; i += WTPB) sm->aw[i] = agent_w[i];
    for (int i = tid; i < 4 * C; i += WTPB) sm->mw[i] = mom_w[i];
    __syncthreads();
    const float ag = agent_gp[0], ab = agent_bp[0];
    const float mg0 = mom_gp[0], mg1 = mom_gp[1], mb0 = mom_bp[0], mb1 = mom_bp[1];

    const int cid = blockIdx.x * WPB + w;
    const int b = cid >> 8;
    const int j = cid & 255;

    int fcur = b * NPTS + g_start[cid];
    float pre1 = g_xw[(size_t)fcur * C + lane];
    float pre2 = g_xw[(size_t)fcur * C + lane + 32];
    float cur1 = 0.f, cur2 = 0.f;

    const int q  = lane & 7;
    const int rg = lane >> 3;

    for (int t = 0; t < CLEN; ++t) {
        const bool useD = (t > 0);

        // ---- gather 32 neighbor rows into smem (overlaps momentum poll) ----
        int myg = b * NPTS + idx[(size_t)fcur * KNBR + lane];
        #pragma unroll
        for (int p = 0; p < 8; ++p) {
            int row = p * 4 + rg;
            int g = __shfl_sync(F, myg, row);
            const float4* src = (const float4*)&g_xw[(size_t)g * C];
            float4 v0 = src[q];
            float4 v1 = src[8 + q];
            *(float4*)&sm->pv[w][row][q * 4]      = v0;
            *(float4*)&sm->pv[w][row][32 + q * 4] = v1;
        }

        if (useD) {
            // ---- poll momentum coefs (published by last-arriving block) ----
            int slot = 2 * t - 1;
            if (tid == 0) {
                while (ldg_acq_s32(&g_rflag[slot][0]) == 0) { }
                sm->bn[0] = ldg_rlx_f32(&g_rcoef[slot][0]);
                sm->bn[1] = ldg_rlx_f32(&g_rcoef[slot][1]);
                sm->bn[2] = ldg_rlx_f32(&g_rcoef[slot][2]);
                sm->bn[3] = ldg_rlx_f32(&g_rcoef[slot][3]);
            }
            __syncthreads();
            // scrambled attention weights (torch .view reshape semantics)
            float att = 0.f;
            if (lane < 2) {
                int f  = 2 * j + lane;
                int ch = f >> 8, jj = f & 255;
                float v0 = ldg_rlx_f32(&g_mm[b * 512 + jj])       * sm->bn[0] + sm->bn[1];
                float v1 = ldg_rlx_f32(&g_mm[b * 512 + 256 + jj]) * sm->bn[2] + sm->bn[3];
                float mx = fmaxf(v0, v1);
                float e0 = expf(v0 - mx), e1 = expf(v1 - mx);
                att = ((ch == 0) ? e0 : e1) / (e0 + e1);
            }
            float att0 = __shfl_sync(F, att, 0);
            float att1 = __shfl_sync(F, att, 1);
            pre1 = cur1 * att0 + pre1 * att1;
            pre2 = cur2 * att0 + pre2 * att1;
            sm->pre[w][lane]      = pre1;
            sm->pre[w][lane + 32] = pre2;
            __syncwarp();
        }

        // ---- fused pre-side dots: agent pd + momentum pre-parts ----
        float pd_l = pre1 * sm->aw[C + lane]   + pre2 * sm->aw[C + lane + 32];
        float p0_l = pre1 * sm->mw[64 + lane]  + pre2 * sm->mw[96 + lane];
        float p1_l = pre1 * sm->mw[192 + lane] + pre2 * sm->mw[224 + lane];
        warpsum3(pd_l, p0_l, p1_l);
        const float pd = pd_l, pdot0 = p0_l, pdot1 = p1_l;
        float anorm = 0.f;
        if (useD) {
            float a1 = cur1 - pre1, a2 = cur2 - pre2;
            anorm = sqrtf(warpsum(a1 * a1 + a2 * a2));
        }
        __syncwarp();   // pv stores visible within warp

        // ---- per-neighbor dots (lane owns neighbor `lane`), incl momentum dm ----
        float pvdot = 0.f, dotv = 0.f, n2 = 0.f, dm0 = 0.f, dm1 = 0.f;
        #pragma unroll
        for (int cc = 0; cc < 16; ++cc) {
            float4 pvv = *(const float4*)&sm->pv[w][lane][cc * 4];
            float4 awv = *(const float4*)&sm->aw[cc * 4];
            float4 m0v = *(const float4*)&sm->mw[cc * 4];
            float4 m1v = *(const float4*)&sm->mw[128 + cc * 4];
            pvdot += pvv.x * awv.x; pvdot += pvv.y * awv.y;
            pvdot += pvv.z * awv.z; pvdot += pvv.w * awv.w;
            dm0 += pvv.x * m0v.x; dm0 += pvv.y * m0v.y;
            dm0 += pvv.z * m0v.z; dm0 += pvv.w * m0v.w;
            dm1 += pvv.x * m1v.x; dm1 += pvv.y * m1v.y;
            dm1 += pvv.z * m1v.z; dm1 += pvv.w * m1v.w;
            if (useD) {
                float4 cuv = *(const float4*)&sm->cur[w][cc * 4];
                float4 prv = *(const float4*)&sm->pre[w][cc * 4];
                float dx;
                dx = pvv.x - cuv.x; dotv += (cuv.x - prv.x) * dx; n2 += dx * dx;
                dx = pvv.y - cuv.y; dotv += (cuv.y - prv.y) * dx; n2 += dx * dx;
                dx = pvv.z - cuv.z; dotv += (cuv.z - prv.z) * dx; n2 += dx * dx;
                dx = pvv.w - cuv.w; dotv += (cuv.w - prv.w) * dx; n2 += dx * dx;
            }
        }
        float raw = pvdot + pd;
        float dfac = 1.f;
        if (useD) {
            float div = fmaxf(anorm * sqrtf(n2), 1e-8f);
            dfac = fminf(fmaxf(1.f + dotv / div, 0.f), 1.f);
        }

        // ---- agent global BN: push-reduce into slot 2t ----
        {
            double ls = warpsumd((double)raw);
            double l2 = warpsumd((double)raw * (double)raw);
            if (lane == 0) { sm->red[w][0] = ls; sm->red[w][1] = l2; }
            __syncthreads();
            int slot = 2 * t;
            if (w == 0) {
                double a  = (lane < WPB) ? sm->red[lane][0] : 0.0;
                double bb = (lane < WPB) ? sm->red[lane][1] : 0.0;
                a = warpsumd(a); bb = warpsumd(bb);
                if (lane < 2) {
                    double vv = (lane == 0) ? a * SCALE_S : bb * SCALE_Q;
                    long long L = __double2ll_rn(vv);
                    atomicAdd(&g_rsum[slot][lane][0], (unsigned long long)L);
                }
                __syncwarp();
                if (lane == 0) {
                    __threadfence();
                    unsigned int old = atomicAdd(&g_rcnt[slot][0], 1u);
                    if (old == WBLK - 1) {
                        __threadfence();
                        double S = (double)(long long)ldg_rlx_u64(&g_rsum[slot][0][0]) / SCALE_S;
                        double Q = (double)(long long)ldg_rlx_u64(&g_rsum[slot][1][0]) / SCALE_Q;
                        double mean = S / 65536.0, var = Q / 65536.0 - mean * mean;
                        float r = (float)(1.0 / sqrt(var + 1e-5));
                        stg_rlx_f32(&g_rcoef[slot][0], r * ag);
                        stg_rlx_f32(&g_rcoef[slot][1], ab - (float)mean * r * ag);
                        stg_rel_s32(&g_rflag[slot][0], 1);
                    }
                }
            }
            if (tid == 0) {
                while (ldg_acq_s32(&g_rflag[slot][0]) == 0) { }
                sm->bn[4] = ldg_rlx_f32(&g_rcoef[slot][0]);
                sm->bn[5] = ldg_rlx_f32(&g_rcoef[slot][1]);
            }
            __syncthreads();
        }

        // ---- straight-through select (argmax, first-index ties) ----
        float score = (raw * sm->bn[4] + sm->bn[5]) * dfac;
        float best = score; int bj = lane;
        #pragma unroll
        for (int o = 16; o; o >>= 1) {
            float os = __shfl_down_sync(F, best, o);
            int   oj = __shfl_down_sync(F, bj, o);
            if (os > best || (os == best && oj < bj)) { best = os; bj = oj; }
        }
        bj = __shfl_sync(F, bj, 0);
        int gsel = __shfl_sync(F, myg, bj);
        float c1 = sm->pv[w][bj][lane];
        float c2 = sm->pv[w][bj][32 + lane];
        cur1 = c1; cur2 = c2;
        sm->cur[w][lane]      = c1;
        sm->cur[w][lane + 32] = c2;
        g_curve[cid][t][lane]      = c1;
        g_curve[cid][t][lane + 32] = c2;
        fcur = gsel;
        __syncwarp();

        // ---- momentum arrival for step t+1 (slot 2t+1) ----
        if (t < CLEN - 1) {
            float m0 = __shfl_sync(F, dm0, bj) + pdot0;
            float m1 = __shfl_sync(F, dm1, bj) + pdot1;
            if (lane == 0) {
                g_mm[b * 512 + j]       = m0;
                g_mm[b * 512 + 256 + j] = m1;
                sm->red[w][0] = (double)m0; sm->red[w][1] = (double)m0 * m0;
                sm->red[w][2] = (double)m1; sm->red[w][3] = (double)m1 * m1;
            }
            __syncthreads();
            int slot = 2 * t + 1;
            if (w == 0) {
                double r0 = (lane < WPB) ? sm->red[lane][0] : 0.0;
                double r1 = (lane < WPB) ? sm->red[lane][1] : 0.0;
                double r2 = (lane < WPB) ? sm->red[lane][2] : 0.0;
                double r3 = (lane < WPB) ? sm->red[lane][3] : 0.0;
                r0 = warpsumd(r0); r1 = warpsumd(r1); r2 = warpsumd(r2); r3 = warpsumd(r3);
                if (lane < 4) {
                    double vv = (lane == 0) ? r0 * SCALE_S :
                                (lane == 1) ? r1 * SCALE_Q :
                                (lane == 2) ? r2 * SCALE_S : r3 * SCALE_Q;
                    long long L = __double2ll_rn(vv);
                    atomicAdd(&g_rsum[slot][lane][0], (unsigned long long)L);
                }
                __syncwarp();
                if (lane == 0) {
                    __threadfence();
                    unsigned int old = atomicAdd(&g_rcnt[slot][0], 1u);
                    if (old == WBLK - 1) {
                        __threadfence();
                        double S0 = (double)(long long)ldg_rlx_u64(&g_rsum[slot][0][0]) / SCALE_S;
                        double Q0 = (double)(long long)ldg_rlx_u64(&g_rsum[slot][1][0]) / SCALE_Q;
                        double S1 = (double)(long long)ldg_rlx_u64(&g_rsum[slot][2][0]) / SCALE_S;
                        double Q1 = (double)(long long)ldg_rlx_u64(&g_rsum[slot][3][0]) / SCALE_Q;
                        double mean0 = S0 / 2048.0, var0 = Q0 / 2048.0 - mean0 * mean0;
                        double mean1 = S1 / 2048.0, var1 = Q1 / 2048.0 - mean1 * mean1;
                        float r0f = (float)(1.0 / sqrt(var0 + 1e-5));
                        float r1f = (float)(1.0 / sqrt(var1 + 1e-5));
                        stg_rlx_f32(&g_rcoef[slot][0], r0f * mg0);
                        stg_rlx_f32(&g_rcoef[slot][1], mb0 - (float)mean0 * r0f * mg0);
                        stg_rlx_f32(&g_rcoef[slot][2], r1f * mg1);
                        stg_rlx_f32(&g_rcoef[slot][3], mb1 - (float)mean1 * r1f * mg1);
                        stg_rel_s32(&g_rflag[slot][0], 1);
                    }
                }
            }
        }
    }

    // ---- epilogue: per-warp transpose of the curve tile, fully coalesced out ----
    __syncwarp();
    {
        const float4* src = (const float4*)&g_curve[cid][lane][0];
        #pragma unroll
        for (int i = 0; i < 16; ++i) {
            float4 v = src[i];
            *(float4*)&sm->pv[w][lane][i * 4] = v;
        }
        __syncwarp();
        #pragma unroll
        for (int h = 0; h < 2; ++h) {
            int c = lane + h * 32;
            size_t obase = (((size_t)(b * C + c)) * CN + j) * CLEN;
            #pragma unroll
            for (int tc = 0; tc < 8; ++tc) {
                float4 v;
                v.x = sm->pv[w][tc * 4 + 0][c];
                v.y = sm->pv[w][tc * 4 + 1][c];
                v.z = sm->pv[w][tc * 4 + 2][c];
                v.w = sm->pv[w][tc * 4 + 3][c];
                *(float4*)&out[obase + tc * 4] = v;
            }
        }
    }
}

// ---------------- host ----------------
extern "C" void kernel_launch(void* const* d_in, const int* in_sizes, int n_in,
                              void* d_out, int out_size) {
    (void)in_sizes; (void)n_in; (void)out_size;
    const float* x       = (const float*)d_in[0];
    /* d_in[1] = xyz (unused by reference) */
    const int*   idx     = (const int*)d_in[2];
    const float* att_w   = (const float*)d_in[3];
    const float* agent_w = (const float*)d_in[4];
    const float* agent_g = (const float*)d_in[5];
    const float* agent_b = (const float*)d_in[6];
    const float* mom_w   = (const float*)d_in[7];
    const float* mom_g   = (const float*)d_in[8];
    const float* mom_b   = (const float*)d_in[9];
    float* out = (float*)d_out;

    cudaFuncSetAttribute(k_topk, cudaFuncAttributeMaxDynamicSharedMemorySize, NPTS * 8);
    cudaFuncSetAttribute(k_walk, cudaFuncAttributeMaxDynamicSharedMemorySize, (int)sizeof(SW));

    k_xw<<<BNB * 256, 256>>>(x, att_w);
    k_topk<<<BNB, 1024, NPTS * 8>>>();
    k_walk<<<WBLK, WTPB, sizeof(SW)>>>(idx, agent_w, agent_g, agent_b,
                                       mom_w, mom_g, mom_b, out);
}